// round 7
// baseline (speedup 1.0000x reference)
#include <cuda_runtime.h>
#include <math.h>
#include <stdint.h>

#define BB    128
#define NQv   32
#define NWv   12
#define NKv   64
#define EMBv  300
#define KP    320
#define FEATv 2048
#define EPSV  1e-5f

#define LDS_ROW 36                 // 32 floats + 4 pad (144B rows, 16B aligned)
#define SBUF (128 * LDS_ROW)
#define NSTAGE 3
#define STAGE_F (2 * SBUF)
#define SMEM_BYTES (NSTAGE * STAGE_F * 4)

// ---------------- scratch (device globals; zero-initialized) ------------------
__device__ float g_Wfr  [EMBv * FEATv];
__device__ float g_kemb [BB * NKv * KP];      // cols 300..319 stay zero
__device__ float g_p0   [BB * NQv * EMBv];
__device__ float g_pembr[BB * NQv * KP];      // cols 300..319 stay zero
__device__ float g_Wc   [EMBv * EMBv];
__device__ float g_bc   [EMBv];

// ---------------- helpers -----------------------------------------------------
__device__ __forceinline__ float rna_tf32(float x) {
    uint32_t u; asm("cvt.rna.tf32.f32 %0, %1;" : "=r"(u) : "f"(x));
    return __uint_as_float(u);
}
__device__ __forceinline__ void mma_tf32(float* d, const float* a, const float* b) {
    asm volatile(
        "mma.sync.aligned.m16n8k8.row.col.f32.tf32.tf32.f32 "
        "{%0,%1,%2,%3}, {%4,%5,%6,%7}, {%8,%9}, {%0,%1,%2,%3};\n"
        : "+f"(d[0]), "+f"(d[1]), "+f"(d[2]), "+f"(d[3])
        : "r"(__float_as_uint(a[0])), "r"(__float_as_uint(a[1])),
          "r"(__float_as_uint(a[2])), "r"(__float_as_uint(a[3])),
          "r"(__float_as_uint(b[0])), "r"(__float_as_uint(b[1])));
}
__device__ __forceinline__ void cp16(uint32_t s, const void* g, int nbytes) {
    asm volatile("cp.async.cg.shared.global [%0], [%1], 16, %2;"
                 :: "r"(s), "l"(g), "r"(nbytes));
}
#define CP_COMMIT() asm volatile("cp.async.commit_group;" ::: "memory")
#define CP_WAIT2()  asm volatile("cp.async.wait_group 2;" ::: "memory")
#define CP_WAIT1()  asm volatile("cp.async.wait_group 1;" ::: "memory")
#define CP_WAIT0()  asm volatile("cp.async.wait_group 0;" ::: "memory")

__device__ __forceinline__ void stage_chunk(
    uint32_t base, int t, int c,
    const float* __restrict__ A, int lda, int aK4, int m0,
    const float* __restrict__ B, int ldb, int bK4, int bRows, int n0)
{
    uint32_t sA = base, sB = base + SBUF * 4;
#pragma unroll
    for (int it = 0; it < 4; it++) {
        int idx = it * 256 + t;
        int m = idx >> 3, p = idx & 7;
        int f4 = c * 8 + p;
        cp16(sA + (uint32_t)(m * LDS_ROW + p * 4) * 4,
             A + (size_t)(m0 + m) * lda + f4 * 4, (f4 < aK4) ? 16 : 0);
    }
#pragma unroll
    for (int it = 0; it < 4; it++) {
        int idx = it * 256 + t;
        int r = idx >> 3, p = idx & 7;
        int f4 = c * 8 + p;
        cp16(sB + (uint32_t)(r * LDS_ROW + p * 4) * 4,
             B + (size_t)(n0 + r) * ldb + f4 * 4,
             (f4 < bK4 && (n0 + r) < bRows) ? 16 : 0);
    }
}

// Vectorized fragment compute: logical K-permutation makes each lane's 8
// per-chunk k-values contiguous -> LDS.128. A and B use the same permutation,
// so products pair up identically; the chunk sum is unchanged.
__device__ __forceinline__ void compute_chunk_v(
    const float* __restrict__ As, const float* __restrict__ Bs,
    int wm, int wn, int g, int tid4, float acc[2][8][4])
{
#pragma unroll
    for (int ksp = 0; ksp < 2; ksp++) {
        float4 av[2][2];
#pragma unroll
        for (int i = 0; i < 2; i++)
#pragma unroll
            for (int h = 0; h < 2; h++) {
                int row = wm * 32 + i * 16 + h * 8 + g;
                av[i][h] = *(const float4*)&As[row * LDS_ROW + tid4 * 8 + ksp * 4];
            }
#pragma unroll
        for (int jh = 0; jh < 2; jh++) {
            float4 bv[4];
#pragma unroll
            for (int jj = 0; jj < 4; jj++) {
                int col = wn * 64 + (jh * 4 + jj) * 8 + g;
                bv[jj] = *(const float4*)&Bs[col * LDS_ROW + tid4 * 8 + ksp * 4];
            }
#pragma unroll
            for (int i = 0; i < 2; i++) {
                float a0[4] = {av[i][0].x, av[i][1].x, av[i][0].y, av[i][1].y};
                float a1[4] = {av[i][0].z, av[i][1].z, av[i][0].w, av[i][1].w};
#pragma unroll
                for (int jj = 0; jj < 4; jj++) {
                    float b0[2] = {bv[jj].x, bv[jj].y};
                    float b1[2] = {bv[jj].z, bv[jj].w};
                    mma_tf32(acc[i][jh * 4 + jj], a0, b0);
                    mma_tf32(acc[i][jh * 4 + jj], a1, b1);
                }
            }
        }
    }
}

// ---------------- small kernels ------------------------------------------------
__global__ void round_wf_kernel(const float* __restrict__ Wf)
{
    int i = blockIdx.x * blockDim.x + threadIdx.x;
    if (i < EMBv * FEATv / 4) {
        float4 v = ((const float4*)Wf)[i];
        v.x = rna_tf32(v.x); v.y = rna_tf32(v.y); v.z = rna_tf32(v.z); v.w = rna_tf32(v.w);
        ((float4*)g_Wfr)[i] = v;
    }
}
__global__ void combine_kernel(const float* __restrict__ Wp, const float* __restrict__ bp,
                               const float* __restrict__ Wm, const float* __restrict__ bm)
{
    int i = blockIdx.x * blockDim.x + threadIdx.x;
    if (i < EMBv * EMBv) g_Wc[i] = rna_tf32(Wp[i] + EPSV * Wm[i]);
    if (i < EMBv)        g_bc[i] = bp[i] + EPSV * bm[i];
}
__global__ void eye_kernel(float* __restrict__ target)
{
    int i = blockIdx.x * blockDim.x + threadIdx.x;
    if (i < BB * BB) target[i] = ((i / BB) == (i % BB)) ? 1.0f : 0.0f;
}

// ---------------- pipelined tf32 GEMM: out = rna(A*B^T + epi) -----------------
__global__ __launch_bounds__(256, 2) void mma_gemm_async(
    const float* __restrict__ A, int lda, int aK4,
    const float* __restrict__ B, int ldb, int bRows, int bK4,
    int nChunks, int mode, const float* __restrict__ bias,
    const float* __restrict__ wv, const int* __restrict__ label,
    float* __restrict__ out)
{
    extern __shared__ float smem[];
    const int m0 = blockIdx.y * 128;
    const int n0 = blockIdx.x * 128;
    const int t  = threadIdx.x;
    const int wid = t >> 5, lane = t & 31;
    const int wm = wid & 3, wn = wid >> 2;
    const int g = lane >> 2, tid4 = lane & 3;

    uint32_t sb = (uint32_t)__cvta_generic_to_shared(smem);

    float acc[2][8][4];
#pragma unroll
    for (int i = 0; i < 2; i++)
#pragma unroll
        for (int j = 0; j < 8; j++)
#pragma unroll
            for (int r = 0; r < 4; r++) acc[i][j][r] = 0.0f;

    stage_chunk(sb, t, 0, A, lda, aK4, m0, B, ldb, bK4, bRows, n0);
    CP_COMMIT();
    stage_chunk(sb + STAGE_F * 4, t, 1, A, lda, aK4, m0, B, ldb, bK4, bRows, n0);
    CP_COMMIT();

    for (int c = 0; c < nChunks; c++) {
        if (c + 2 < nChunks) { CP_WAIT1(); } else { CP_WAIT0(); }
        __syncthreads();
        if (c + 2 < nChunks) {       // prefetch BEFORE compute (buffer (c+2)%3 is free)
            stage_chunk(sb + ((c + 2) % 3) * STAGE_F * 4, t, c + 2,
                        A, lda, aK4, m0, B, ldb, bK4, bRows, n0);
            CP_COMMIT();
        }
        const float* As = smem + (c % 3) * STAGE_F;
        compute_chunk_v(As, As + SBUF, wm, wn, g, tid4, acc);
    }

#pragma unroll
    for (int i = 0; i < 2; i++) {
#pragma unroll
        for (int rh = 0; rh < 2; rh++) {
            int gm = m0 + wm * 32 + i * 16 + g + rh * 8;
            const float* wrow = (mode == 0) ? (wv + (size_t)label[gm] * EMBv) : nullptr;
#pragma unroll
            for (int j = 0; j < 8; j++) {
#pragma unroll
                for (int q = 0; q < 2; q++) {
                    int gn = n0 + wn * 64 + j * 8 + 2 * tid4 + q;
                    if (gn < EMBv) {
                        float v = acc[i][j][rh * 2 + q] + bias[gn];
                        if (mode == 0) v += wrow[gn];
                        out[(size_t)gm * KP + gn] = rna_tf32(v);
                    }
                }
            }
        }
    }
}

// ---------------- attmap: pipelined MMA + fused softmax/max/sum ---------------
#define CS_LD 129
__global__ __launch_bounds__(256, 2) void attmap_mma_async(
    float* __restrict__ logits, float* __restrict__ attsum,
    const int* __restrict__ num_query)
{
    extern __shared__ float smem[];
    const int m0 = blockIdx.y * 128;
    const int n0 = blockIdx.x * 128;
    const int t  = threadIdx.x;
    const int wid = t >> 5, lane = t & 31;
    const int wm = wid & 3, wn = wid >> 2;
    const int g = lane >> 2, tid4 = lane & 3;

    uint32_t sb = (uint32_t)__cvta_generic_to_shared(smem);

    float acc[2][8][4];
#pragma unroll
    for (int i = 0; i < 2; i++)
#pragma unroll
        for (int j = 0; j < 8; j++)
#pragma unroll
            for (int r = 0; r < 4; r++) acc[i][j][r] = 0.0f;

    const int NCH = KP / 32;
    stage_chunk(sb, t, 0, g_pembr, KP, KP / 4, m0, g_kemb, KP, KP / 4, BB * NKv, n0);
    CP_COMMIT();
    stage_chunk(sb + STAGE_F * 4, t, 1, g_pembr, KP, KP / 4, m0,
                g_kemb, KP, KP / 4, BB * NKv, n0);
    CP_COMMIT();

    for (int c = 0; c < NCH; c++) {
        if (c + 2 < NCH) { CP_WAIT1(); } else { CP_WAIT0(); }
        __syncthreads();
        if (c + 2 < NCH) {
            stage_chunk(sb + ((c + 2) % 3) * STAGE_F * 4, t, c + 2,
                        g_pembr, KP, KP / 4, m0, g_kemb, KP, KP / 4, BB * NKv, n0);
            CP_COMMIT();
        }
        const float* As = smem + (c % 3) * STAGE_F;
        compute_chunk_v(As, As + SBUF, wm, wn, g, tid4, acc);
    }
    __syncthreads();

    float* Cs = smem;
#pragma unroll
    for (int i = 0; i < 2; i++) {
#pragma unroll
        for (int rh = 0; rh < 2; rh++) {
            int row = wm * 32 + i * 16 + g + rh * 8;
#pragma unroll
            for (int j = 0; j < 8; j++) {
                int col = wn * 64 + j * 8 + 2 * tid4;
                Cs[row * CS_LD + col]     = acc[i][j][rh * 2 + 0];
                Cs[row * CS_LD + col + 1] = acc[i][j][rh * 2 + 1];
            }
        }
    }
    __syncthreads();

    const int bk = wid & 3, ah = wid >> 2;
    const int b = (m0 >> 5) + bk;
    const int a = (n0 >> 6) + ah;
    float* row = &Cs[(bk * 32 + lane) * CS_LD + ah * 64];

    float mx = -1e30f;
#pragma unroll
    for (int v = 0; v < 64; v++) mx = fmaxf(mx, row[v]);

    float s = mx;
#pragma unroll
    for (int o = 16; o; o >>= 1) s += __shfl_xor_sync(0xffffffffu, s, o);
    if (lane == 0) logits[b * BB + a] = s / (float)num_query[b];

    float se = 0.f;
#pragma unroll
    for (int v = 0; v < 64; v++) { float e = __expf(row[v] - mx); se += e; row[v] = e; }
    const float rinv = 1.0f / se;
#pragma unroll
    for (int v = 0; v < 64; v++) row[v] *= rinv;
    __syncthreads();

    {
        float s0 = 0.f, s1 = 0.f;
        const float* base = &Cs[(bk * 32) * CS_LD + ah * 64];
#pragma unroll
        for (int q = 0; q < 32; q++) {
            s0 += base[q * CS_LD + lane];
            s1 += base[q * CS_LD + lane + 32];
        }
        attsum[((size_t)b * BB + a) * NKv + lane]      = s0;
        attsum[((size_t)b * BB + a) * NKv + lane + 32] = s1;
    }
}

// ---------------- p0 via MMA: one CTA per b -----------------------------------
#define KSB_LD 324
#define PA_LD  36
#define PABUF  (128 * PA_LD)
#define P0_SMEM_F (64 * KSB_LD + 3 * PABUF + 384 + 384 + 384)
#define P0_SMEM_BYTES (P0_SMEM_F * 4)

__global__ __launch_bounds__(256) void p0_mma_kernel(const int* __restrict__ query,
                                                     const float* __restrict__ wv)
{
    extern __shared__ float ps[];
    float* Ks    = ps;                       // [64][KSB_LD]
    float* Ab    = Ks + 64 * KSB_LD;         // 3 x [128][PA_LD]
    float* qma   = Ab + 3 * PABUF;           // [384]
    float* qnorm = qma + 384;                // [384]
    int*   qi    = (int*)(qnorm + 384);      // [384]

    const int b = blockIdx.x;
    const int t = threadIdx.x;
    const int wid = t >> 5, lane = t & 31;
    const int g = lane >> 2, tid4 = lane & 3;

    uint32_t sb = (uint32_t)__cvta_generic_to_shared(ps);
    const uint32_t ks_sb = sb;
    const uint32_t ab_sb = sb + 64 * KSB_LD * 4;

    for (int idx = t; idx < 384; idx += 256)
        qi[idx] = query[b * 384 + idx];
    __syncthreads();

    {
        const float* kb = g_kemb + (size_t)b * NKv * KP;
        for (int idx = t; idx < 64 * 80; idx += 256) {
            int r = idx / 80, f4 = idx % 80;
            cp16(ks_sb + (uint32_t)(r * KSB_LD + f4 * 4) * 4,
                 kb + (size_t)r * KP + f4 * 4, 16);
        }
        CP_COMMIT();
    }

    auto stage_a = [&](int cc, int buf) {
        const int msub = cc / 10, kc = cc % 10;
        uint32_t base = ab_sb + (uint32_t)buf * PABUF * 4;
#pragma unroll
        for (int it = 0; it < 4; it++) {
            int idx = it * 256 + t;
            int row = idx >> 3, p = idx & 7;
            int f4 = kc * 8 + p;
            int ridx = msub * 128 + row;
            cp16(base + (uint32_t)(row * PA_LD + p * 4) * 4,
                 wv + (size_t)qi[ridx] * EMBv + f4 * 4,
                 (f4 < 75) ? 16 : 0);
        }
    };

    stage_a(0, 0); CP_COMMIT();
    stage_a(1, 1); CP_COMMIT();

    float acc[8][4];
#pragma unroll
    for (int j = 0; j < 8; j++)
#pragma unroll
        for (int r = 0; r < 4; r++) acc[j][r] = 0.0f;

    const float scale = rsqrtf((float)EMBv);

    for (int cc = 0; cc < 30; cc++) {
        if (cc + 2 < 30) { stage_a(cc + 2, (cc + 2) % 3); CP_COMMIT(); }
        if (cc < 28)      { CP_WAIT2(); }
        else if (cc == 28){ CP_WAIT1(); }
        else              { CP_WAIT0(); }
        __syncthreads();

        const float* As = Ab + (cc % 3) * PABUF;
        const int kc = cc % 10;
        const float* Bk = Ks + kc * 32;

#pragma unroll
        for (int ksp = 0; ksp < 2; ksp++) {
            float4 av[2];
#pragma unroll
            for (int h = 0; h < 2; h++) {
                int row = wid * 16 + h * 8 + g;
                av[h] = *(const float4*)&As[row * PA_LD + tid4 * 8 + ksp * 4];
            }
            float a0[4] = {av[0].x, av[1].x, av[0].y, av[1].y};
            float a1[4] = {av[0].z, av[1].z, av[0].w, av[1].w};
#pragma unroll
            for (int j = 0; j < 8; j++) {
                int col = j * 8 + g;
                float4 bv = *(const float4*)&Bk[col * KSB_LD + tid4 * 8 + ksp * 4];
                float b0[2] = {bv.x, bv.y};
                float b1[2] = {bv.z, bv.w};
                mma_tf32(acc[j], a0, b0);
                mma_tf32(acc[j], a1, b1);
            }
        }

        if (kc == 9) {
            const int msub = cc / 10;
#pragma unroll
            for (int rh = 0; rh < 2; rh++) {
                float mx = -1e30f;
#pragma unroll
                for (int j = 0; j < 8; j++) {
                    mx = fmaxf(mx, acc[j][rh * 2]);
                    mx = fmaxf(mx, acc[j][rh * 2 + 1]);
                }
                mx = fmaxf(mx, __shfl_xor_sync(0xffffffffu, mx, 1));
                mx = fmaxf(mx, __shfl_xor_sync(0xffffffffu, mx, 2));
                float mxs = mx * scale;
                float se = 0.f;
#pragma unroll
                for (int j = 0; j < 8; j++) {
                    se += __expf(acc[j][rh * 2] * scale - mxs);
                    se += __expf(acc[j][rh * 2 + 1] * scale - mxs);
                }
                se += __shfl_xor_sync(0xffffffffu, se, 1);
                se += __shfl_xor_sync(0xffffffffu, se, 2);
                if (tid4 == 0)
                    qma[msub * 128 + wid * 16 + rh * 8 + g] = 1.0f / se;
            }
#pragma unroll
            for (int j = 0; j < 8; j++)
#pragma unroll
                for (int r = 0; r < 4; r++) acc[j][r] = 0.0f;
        }
    }
    __syncthreads();

    if (t < 32) {
        const int q = t;
        float m2 = -1e30f;
#pragma unroll
        for (int w = 0; w < NWv; w++) m2 = fmaxf(m2, qma[q * NWv + w]);
        float s2 = 0.f;
        float e[NWv];
#pragma unroll
        for (int w = 0; w < NWv; w++) { e[w] = __expf(qma[q * NWv + w] - m2); s2 += e[w]; }
        float inv = 1.0f / s2;
#pragma unroll
        for (int w = 0; w < NWv; w++) qnorm[q * NWv + w] = e[w] * inv;
    }
    __syncthreads();

    for (int idx = t; idx < NQv * EMBv; idx += 256) {
        int q = idx / EMBv, d = idx % EMBv;
        float s = 0.f;
#pragma unroll
        for (int w = 0; w < NWv; w++)
            s += qnorm[q * NWv + w] * wv[(size_t)qi[q * NWv + w] * EMBv + d];
        g_p0[(size_t)(b * NQv + q) * EMBv + d] = rna_tf32(s);
    }
}

// ---------------- launch ------------------------------------------------------
extern "C" void kernel_launch(void* const* d_in, const int* in_sizes, int n_in,
                              void* d_out, int out_size)
{
    const int*   query     = (const int*)  d_in[1];
    const int*   label     = (const int*)  d_in[2];
    const float* feature   = (const float*)d_in[3];
    const int*   num_query = (const int*)  d_in[7];
    const float* wv        = (const float*)d_in[8];
    const float* Wp        = (const float*)d_in[9];
    const float* bp        = (const float*)d_in[10];
    const float* Wm        = (const float*)d_in[11];
    const float* bm        = (const float*)d_in[12];
    const float* Wf        = (const float*)d_in[13];
    const float* bf        = (const float*)d_in[14];

    float* out    = (float*)d_out;
    float* logits = out;
    float* target = out + BB * BB;
    float* attsum = out + 2 * BB * BB;

    static int smem_set = 0;
    if (!smem_set) {
        cudaFuncSetAttribute(mma_gemm_async,
                             cudaFuncAttributeMaxDynamicSharedMemorySize, SMEM_BYTES);
        cudaFuncSetAttribute(attmap_mma_async,
                             cudaFuncAttributeMaxDynamicSharedMemorySize, SMEM_BYTES);
        cudaFuncSetAttribute(p0_mma_kernel,
                             cudaFuncAttributeMaxDynamicSharedMemorySize, P0_SMEM_BYTES);
        smem_set = 1;
    }

    float* d_Wfr; cudaGetSymbolAddress((void**)&d_Wfr, g_Wfr);
    float* d_Wc;  cudaGetSymbolAddress((void**)&d_Wc,  g_Wc);
    float* d_bc;  cudaGetSymbolAddress((void**)&d_bc,  g_bc);
    float* d_p0;  cudaGetSymbolAddress((void**)&d_p0,  g_p0);
    float* d_ke;  cudaGetSymbolAddress((void**)&d_ke,  g_kemb);
    float* d_pe;  cudaGetSymbolAddress((void**)&d_pe,  g_pembr);

    round_wf_kernel<<<(EMBv * FEATv / 4 + 255) / 256, 256>>>(Wf);
    combine_kernel<<<(EMBv * EMBv + 255) / 256, 256>>>(Wp, bp, Wm, bm);

    // k_emb = rna( feature @ Wf^T + wv[label] + bf )  [8192 x 300 x 2048]
    mma_gemm_async<<<dim3(3, 64), 256, SMEM_BYTES>>>(
        feature, FEATv, FEATv / 4, d_Wfr, FEATv, EMBv, FEATv / 4,
        FEATv / 32, 0, bf, wv, label, d_ke);

    // p0 via per-b MMA
    p0_mma_kernel<<<BB, 256, P0_SMEM_BYTES>>>(query, wv);

    // p_emb = rna( p0 @ Wc^T + bc )  [4096 x 300 x 300]
    mma_gemm_async<<<dim3(3, 32), 256, SMEM_BYTES>>>(
        d_p0, EMBv, 75, d_Wc, EMBv, EMBv, 75,
        10, 1, d_bc, nullptr, nullptr, d_pe);

    // attmap + fused softmax/max/sum  [4096 x 8192 x 320]
    attmap_mma_async<<<dim3(64, 32), 256, SMEM_BYTES>>>(logits, attsum, num_query);

    eye_kernel<<<(BB * BB + 255) / 256, 256>>>(target);
}